// round 2
// baseline (speedup 1.0000x reference)
#include <cuda_runtime.h>
#include <math.h>

#define BATCH 2
#define SEQ   2048
#define EMB   512
#define NH    8
#define HD    64
#define BS    (BATCH*SEQ)      /* 4096 */
#define W1LD  (EMB+NH)         /* 520  */

// ---------------- scratch (device globals; no allocation allowed) ----------------
__device__ float g_q[BS*EMB];
__device__ float g_k[BS*EMB];
__device__ float g_v[BS*EMB];
__device__ float g_scores[(size_t)BATCH*NH*SEQ*SEQ];   // 256 MiB
__device__ float g_ewm[(size_t)BATCH*SEQ*SEQ];         // mean edge weights
__device__ float g_ewk[(size_t)BATCH*SEQ*SEQ];         // masked edge weights
__device__ float g_invnn[BS];
__device__ float g_mid[BS*EMB];
__device__ float g_pre[BS*EMB];
__device__ float g_accv[BS*EMB];
__device__ float g_accx[BS*EMB];
__device__ float g_bm1eff[EMB];

// ---------------- fast exp on the FMA pipe (MUFU is 0.5/SM/cyc on sm_103a) -------
__device__ __forceinline__ float fast_exp(float x) {
    x = fmaxf(x, -80.0f);
    float t  = x * 1.4426950408889634f;      // x * log2(e)
    float fi = floorf(t + 0.5f);
    float f  = t - fi;                        // f in (-0.5, 0.5]
    float u  = f * 0.6931471805599453f;       // back to natural log domain
    // degree-5 Taylor of e^u, |u| <= 0.347 -> rel err ~2e-6
    float p = 1.0f + u*(1.0f + u*(0.5f + u*(0.16666667f + u*(0.041666667f + u*0.0083333333f))));
    int ei = (int)fi;
    return __int_as_float((ei + 127) << 23) * p;
}

// ---------------- generic SGEMM: C = alpha * A @ op(B) + bias, optional GELU -----
// TB=true:  B is [N,K] row-major (C = A @ B^T)
// TB=false: B is [K,N] row-major (C = A @ B)
// All of M, N multiples of 64; K multiple of 16. No bounds checks needed.
template<bool TB, bool GELU>
__global__ __launch_bounds__(256)
void sgemm(const float* __restrict__ A, const float* __restrict__ B,
           const float* __restrict__ bias, float* __restrict__ C,
           int M, int N, int K, int lda, int ldb, int ldc,
           long long sA, long long sB, long long sC, float alpha)
{
    __shared__ __align__(16) float As[16][68];
    __shared__ __align__(16) float Bs[16][68];

    A += (long long)blockIdx.z * sA;
    B += (long long)blockIdx.z * sB;
    C += (long long)blockIdx.z * sC;

    const int m0 = blockIdx.y * 64;
    const int n0 = blockIdx.x * 64;
    const int tid = threadIdx.x;
    const int tx = tid & 15;      // N direction
    const int ty = tid >> 4;      // M direction

    float acc[4][4];
#pragma unroll
    for (int i = 0; i < 4; i++)
#pragma unroll
        for (int j = 0; j < 4; j++) acc[i][j] = 0.0f;

    for (int k0 = 0; k0 < K; k0 += 16) {
#pragma unroll
        for (int r = 0; r < 4; r++) {
            int l = tid + r * 256;
            int mm = l >> 4, kk = l & 15;
            As[kk][mm] = A[(long long)(m0 + mm) * lda + (k0 + kk)];
        }
        if (TB) {
#pragma unroll
            for (int r = 0; r < 4; r++) {
                int l = tid + r * 256;
                int nn = l >> 4, kk = l & 15;
                Bs[kk][nn] = B[(long long)(n0 + nn) * ldb + (k0 + kk)];
            }
        } else {
#pragma unroll
            for (int r = 0; r < 4; r++) {
                int l = tid + r * 256;
                int kk = l >> 6, nn = l & 63;
                Bs[kk][nn] = B[(long long)(k0 + kk) * ldb + (n0 + nn)];
            }
        }
        __syncthreads();
#pragma unroll
        for (int kk = 0; kk < 16; kk++) {
            float4 av = *(const float4*)&As[kk][ty * 4];
            float4 bv = *(const float4*)&Bs[kk][tx * 4];
            float a_[4] = {av.x, av.y, av.z, av.w};
            float b_[4] = {bv.x, bv.y, bv.z, bv.w};
#pragma unroll
            for (int i = 0; i < 4; i++)
#pragma unroll
                for (int j = 0; j < 4; j++)
                    acc[i][j] += a_[i] * b_[j];
        }
        __syncthreads();
    }

#pragma unroll
    for (int i = 0; i < 4; i++) {
        int m = m0 + ty * 4 + i;
#pragma unroll
        for (int j = 0; j < 4; j++) {
            int n = n0 + tx * 4 + j;
            float v = acc[i][j] * alpha;
            if (bias) v += bias[n];
            if (GELU) v = 0.5f * v * (1.0f + erff(v * 0.70710678118654752f));
            C[(long long)m * ldc + n] = v;
        }
    }
}

// ---------------- effective MLP bias: edge_features == 1/S analytically ----------
__global__ void bm1eff_kernel(const float* __restrict__ Wm1,
                              const float* __restrict__ bm1,
                              float* __restrict__ out)
{
    int e = blockIdx.x * blockDim.x + threadIdx.x;
    if (e < EMB) {
        float s = 0.0f;
#pragma unroll
        for (int h = 0; h < NH; h++) s += Wm1[(long long)e * W1LD + EMB + h];
        out[e] = bm1[e] + s * (1.0f / (float)SEQ);
    }
}

// ---------------- softmax over j per (b,i,h); emit ew_mean, masked, 1/nn ---------
// One block per (b,i). 8 warps, warp w owns head w. All 8 head-rows (64 KB) in smem.
__global__ __launch_bounds__(256)
void softmax_ew_kernel(const float* __restrict__ scores,
                       float* __restrict__ ewm, float* __restrict__ ewk,
                       float* __restrict__ invnn)
{
    extern __shared__ float sm[];            // NH * SEQ floats
    __shared__ float sinv[NH];
    __shared__ int   scnt[NH];

    const int bi = blockIdx.x;               // 0..BS-1
    const int b  = bi / SEQ;
    const int i  = bi % SEQ;
    const int tid = threadIdx.x;

    const float* base0 = scores + ((size_t)(b * NH) * SEQ + (size_t)i) * SEQ;
    const size_t hstride = (size_t)SEQ * SEQ;

    for (int idx = tid; idx < NH * SEQ; idx += 256) {
        int h = idx >> 11;                   // /2048
        int j = idx & (SEQ - 1);
        sm[idx] = base0[(size_t)h * hstride + j];
    }
    __syncthreads();

    const int w = tid >> 5, lane = tid & 31;
    {
        float m = -1e30f;
        for (int j = lane; j < SEQ; j += 32) m = fmaxf(m, sm[w * SEQ + j]);
#pragma unroll
        for (int o = 16; o > 0; o >>= 1) m = fmaxf(m, __shfl_xor_sync(0xffffffffu, m, o));
        float z = 0.0f;
        for (int j = lane; j < SEQ; j += 32) {
            float e = fast_exp(sm[w * SEQ + j] - m);
            sm[w * SEQ + j] = e;
            z += e;
        }
#pragma unroll
        for (int o = 16; o > 0; o >>= 1) z += __shfl_xor_sync(0xffffffffu, z, o);
        if (lane == 0) sinv[w] = 1.0f / z;
    }
    __syncthreads();

    float inv[NH];
#pragma unroll
    for (int h = 0; h < NH; h++) inv[h] = sinv[h] * (1.0f / (float)NH);

    int cnt = 0;
    const size_t obase = (size_t)bi * SEQ;
    for (int j = tid; j < SEQ; j += 256) {
        float ew = 0.0f;
#pragma unroll
        for (int h = 0; h < NH; h++) ew += sm[h * SEQ + j] * inv[h];
        ewm[obase + j] = ew;
        bool adj = ew > 0.1f;
        ewk[obase + j] = adj ? ew : 0.0f;
        cnt += adj ? 1 : 0;
    }
#pragma unroll
    for (int o = 16; o > 0; o >>= 1) cnt += __shfl_xor_sync(0xffffffffu, cnt, o);
    if (lane == 0) scnt[w] = cnt;
    __syncthreads();
    if (tid == 0) {
        int c = 0;
#pragma unroll
        for (int h = 0; h < NH; h++) c += scnt[h];
        float f = (float)c;
        if (f < 1.0f) f = 1.0f;
        invnn[bi] = 1.0f / f;
    }
}

// ---------------- elementwise: pre += accx * invnn + accv ------------------------
__global__ void combine_kernel(float* __restrict__ pre,
                               const float* __restrict__ accx,
                               const float* __restrict__ accv,
                               const float* __restrict__ invnn)
{
    int idx = blockIdx.x * blockDim.x + threadIdx.x;
    if (idx < BS * EMB) {
        int bi = idx >> 9;   // / EMB
        pre[idx] += accx[idx] * invnn[bi] + accv[idx];
    }
}

// ---------------- driver ---------------------------------------------------------
extern "C" void kernel_launch(void* const* d_in, const int* in_sizes, int n_in,
                              void* d_out, int out_size)
{
    const float* x   = (const float*)d_in[0];
    const float* Wq  = (const float*)d_in[1];
    const float* bq  = (const float*)d_in[2];
    const float* Wk  = (const float*)d_in[3];
    const float* bk  = (const float*)d_in[4];
    const float* Wv  = (const float*)d_in[5];
    const float* bv  = (const float*)d_in[6];
    const float* Wm1 = (const float*)d_in[7];
    const float* bm1 = (const float*)d_in[8];
    const float* Wm2 = (const float*)d_in[9];
    const float* bm2 = (const float*)d_in[10];
    const float* Wo  = (const float*)d_in[11];
    const float* bo  = (const float*)d_in[12];
    float* out = (float*)d_out;

    float *q, *k, *v, *scores, *ewm, *ewk, *invnn, *mid, *pre, *accv, *accx, *bm1eff;
    cudaGetSymbolAddress((void**)&q,      g_q);
    cudaGetSymbolAddress((void**)&k,      g_k);
    cudaGetSymbolAddress((void**)&v,      g_v);
    cudaGetSymbolAddress((void**)&scores, g_scores);
    cudaGetSymbolAddress((void**)&ewm,    g_ewm);
    cudaGetSymbolAddress((void**)&ewk,    g_ewk);
    cudaGetSymbolAddress((void**)&invnn,  g_invnn);
    cudaGetSymbolAddress((void**)&mid,    g_mid);
    cudaGetSymbolAddress((void**)&pre,    g_pre);
    cudaGetSymbolAddress((void**)&accv,   g_accv);
    cudaGetSymbolAddress((void**)&accx,   g_accx);
    cudaGetSymbolAddress((void**)&bm1eff, g_bm1eff);

    // effective MLP bias (edge_features == 1/S)
    bm1eff_kernel<<<1, 512>>>(Wm1, bm1, bm1eff);

    // QKV projections: [4096,512] = x @ W^T + b
    dim3 gP(EMB / 64, BS / 64, 1);
    sgemm<true,  false><<<gP, 256>>>(x, Wq, bq, q, BS, EMB, EMB, EMB, EMB, EMB, 0, 0, 0, 1.0f);
    sgemm<true,  false><<<gP, 256>>>(x, Wk, bk, k, BS, EMB, EMB, EMB, EMB, EMB, 0, 0, 0, 1.0f);
    sgemm<true,  false><<<gP, 256>>>(x, Wv, bv, v, BS, EMB, EMB, EMB, EMB, EMB, 0, 0, 0, 1.0f);

    // scores[b,h] = scale * q_h @ k_h^T  (z = head; per-batch launch)
    dim3 gS(SEQ / 64, SEQ / 64, NH);
    for (int b = 0; b < BATCH; b++) {
        sgemm<true, false><<<gS, 256>>>(
            q + (size_t)b * SEQ * EMB, k + (size_t)b * SEQ * EMB, nullptr,
            scores + (size_t)b * NH * SEQ * SEQ,
            SEQ, SEQ, HD, EMB, EMB, SEQ,
            64LL, 64LL, (long long)SEQ * SEQ, 0.125f);
    }

    // softmax + mean-over-heads + threshold mask + neighbor counts
    cudaFuncSetAttribute(softmax_ew_kernel,
                         cudaFuncAttributeMaxDynamicSharedMemorySize, NH * SEQ * 4);
    softmax_ew_kernel<<<BS, 256, NH * SEQ * 4>>>(scores, ewm, ewk, invnn);

    // aggregations: accv = ewm @ v ; accx = ewk @ x  (z = batch)
    dim3 gA(EMB / 64, SEQ / 64, BATCH);
    sgemm<false, false><<<gA, 256>>>(ewm, v, nullptr, accv, SEQ, EMB, SEQ, SEQ, EMB, EMB,
                                     (long long)SEQ * SEQ, (long long)SEQ * EMB, (long long)SEQ * EMB, 1.0f);
    sgemm<false, false><<<gA, 256>>>(ewk, x, nullptr, accx, SEQ, EMB, SEQ, SEQ, EMB, EMB,
                                     (long long)SEQ * SEQ, (long long)SEQ * EMB, (long long)SEQ * EMB, 1.0f);

    // gated MLP: mid = gelu(x @ Wm1[:, :E]^T + bm1_eff); pre = mid @ Wm2^T + bm2
    sgemm<true, true ><<<gP, 256>>>(x,   Wm1, bm1eff, mid, BS, EMB, EMB, EMB, W1LD, EMB, 0, 0, 0, 1.0f);
    sgemm<true, false><<<gP, 256>>>(mid, Wm2, bm2,    pre, BS, EMB, EMB, EMB, EMB,  EMB, 0, 0, 0, 1.0f);

    // pre += messages + attended
    combine_kernel<<<(BS * EMB + 255) / 256, 256>>>(pre, accx, accv, invnn);

    // out = pre @ Wo^T + bo
    sgemm<true, false><<<gP, 256>>>(pre, Wo, bo, out, BS, EMB, EMB, EMB, EMB, EMB, 0, 0, 0, 1.0f);
}

// round 9
// speedup vs baseline: 1.1465x; 1.1465x over previous
#include <cuda_runtime.h>
#include <math.h>

#define BATCH 2
#define SEQ   2048
#define EMB   512
#define NH    8
#define HD    64
#define BS    (BATCH*SEQ)      /* 4096 */
#define W1LD  (EMB+NH)         /* 520  */

// ---------------- scratch (device globals; no allocation allowed) ----------------
__device__ float g_q[BS*EMB];
__device__ float g_k[BS*EMB];
__device__ float g_v[BS*EMB];
__device__ float g_scores[(size_t)BATCH*NH*SEQ*SEQ];   // 256 MiB
__device__ float g_ewm[(size_t)BATCH*SEQ*SEQ];         // mean edge weights
__device__ float g_ewk[(size_t)BATCH*SEQ*SEQ];         // masked edge weights
__device__ float g_invnn[BS];
__device__ float g_mid[BS*EMB];
__device__ float g_pre[BS*EMB];
__device__ float g_accv[BS*EMB];
__device__ float g_accx[BS*EMB];
__device__ float g_bm1eff[EMB];

// ---------------- fast exp on the FMA pipe (MUFU is 0.5/SM/cyc on sm_103a) -------
__device__ __forceinline__ float fast_exp(float x) {
    x = fmaxf(x, -80.0f);
    float t  = x * 1.4426950408889634f;
    float fi = floorf(t + 0.5f);
    float f  = t - fi;
    float u  = f * 0.6931471805599453f;
    float p = 1.0f + u*(1.0f + u*(0.5f + u*(0.16666667f + u*(0.041666667f + u*0.0083333333f))));
    int ei = (int)fi;
    return __int_as_float((ei + 127) << 23) * p;
}

// ================= 128x128 tile, BK=16, 8x8 microtile, double-buffered SGEMM =====
// C[M,N] = alpha * A @ op(B) + bias, optional exact GELU.
// TB=true:  B is [N,K] row-major (C = A @ B^T);  TB=false: B is [K,N] row-major.
// Requires: M,N multiples of 128; K multiple of 16. Grid: (N/128, M/128, Z).
template<bool TB, bool GELU>
__global__ __launch_bounds__(256)
void sgemm128(const float* __restrict__ A, const float* __restrict__ B,
              const float* __restrict__ bias, float* __restrict__ C,
              int K, int lda, int ldb, int ldc,
              long long sA, long long sB, long long sC, float alpha)
{
    __shared__ __align__(16) float As[2][16][132];
    __shared__ __align__(16) float Bs[2][16][132];

    A += (long long)blockIdx.z * sA;
    B += (long long)blockIdx.z * sB;
    C += (long long)blockIdx.z * sC;

    const int m0 = blockIdx.y * 128;
    const int n0 = blockIdx.x * 128;
    const int tid = threadIdx.x;
    const int tx = tid & 15;          // N direction (8 cols each)
    const int ty = tid >> 4;          // M direction (8 rows each)

    const int aRow = tid >> 2;
    const int aK4  = (tid & 3) << 2;
    const int bK   = tid >> 5;
    const int bN4  = (tid & 31) << 2;

    float4 a0, a1, b0, b1;

    // ---- prologue: load tile k0=0 ----
    {
        const float* Ap = A + (long long)m0 * lda;
        a0 = *(const float4*)&Ap[(long long)aRow        * lda + aK4];
        a1 = *(const float4*)&Ap[(long long)(aRow + 64) * lda + aK4];
        if (TB) {
            const float* Bp = B + (long long)n0 * ldb;
            b0 = *(const float4*)&Bp[(long long)aRow        * ldb + aK4];
            b1 = *(const float4*)&Bp[(long long)(aRow + 64) * ldb + aK4];
        } else {
            const float* Bp = B + n0;
            b0 = *(const float4*)&Bp[(long long)bK       * ldb + bN4];
            b1 = *(const float4*)&Bp[(long long)(bK + 8) * ldb + bN4];
        }
    }
    {
        As[0][aK4+0][aRow] = a0.x; As[0][aK4+1][aRow] = a0.y;
        As[0][aK4+2][aRow] = a0.z; As[0][aK4+3][aRow] = a0.w;
        As[0][aK4+0][aRow+64] = a1.x; As[0][aK4+1][aRow+64] = a1.y;
        As[0][aK4+2][aRow+64] = a1.z; As[0][aK4+3][aRow+64] = a1.w;
        if (TB) {
            Bs[0][aK4+0][aRow] = b0.x; Bs[0][aK4+1][aRow] = b0.y;
            Bs[0][aK4+2][aRow] = b0.z; Bs[0][aK4+3][aRow] = b0.w;
            Bs[0][aK4+0][aRow+64] = b1.x; Bs[0][aK4+1][aRow+64] = b1.y;
            Bs[0][aK4+2][aRow+64] = b1.z; Bs[0][aK4+3][aRow+64] = b1.w;
        } else {
            *(float4*)&Bs[0][bK    ][bN4] = b0;
            *(float4*)&Bs[0][bK + 8][bN4] = b1;
        }
    }
    __syncthreads();

    float acc[8][8];
#pragma unroll
    for (int i = 0; i < 8; i++)
#pragma unroll
        for (int j = 0; j < 8; j++) acc[i][j] = 0.0f;

    int buf = 0;
    for (int k0 = 0; k0 < K; k0 += 16) {
        const int k1 = k0 + 16;
        const bool more = (k1 < K);
        if (more) {
            const float* Ap = A + (long long)m0 * lda + k1;
            a0 = *(const float4*)&Ap[(long long)aRow        * lda + aK4];
            a1 = *(const float4*)&Ap[(long long)(aRow + 64) * lda + aK4];
            if (TB) {
                const float* Bp = B + (long long)n0 * ldb + k1;
                b0 = *(const float4*)&Bp[(long long)aRow        * ldb + aK4];
                b1 = *(const float4*)&Bp[(long long)(aRow + 64) * ldb + aK4];
            } else {
                const float* Bp = B + (long long)k1 * ldb + n0;
                b0 = *(const float4*)&Bp[(long long)bK       * ldb + bN4];
                b1 = *(const float4*)&Bp[(long long)(bK + 8) * ldb + bN4];
            }
        }

#pragma unroll
        for (int kk = 0; kk < 16; kk++) {
            float af[8], bf[8];
            *(float4*)&af[0] = *(const float4*)&As[buf][kk][ty * 8];
            *(float4*)&af[4] = *(const float4*)&As[buf][kk][ty * 8 + 4];
            *(float4*)&bf[0] = *(const float4*)&Bs[buf][kk][tx * 8];
            *(float4*)&bf[4] = *(const float4*)&Bs[buf][kk][tx * 8 + 4];
#pragma unroll
            for (int i = 0; i < 8; i++)
#pragma unroll
                for (int j = 0; j < 8; j++)
                    acc[i][j] = fmaf(af[i], bf[j], acc[i][j]);
        }

        if (more) {
            const int nb = buf ^ 1;
            As[nb][aK4+0][aRow] = a0.x; As[nb][aK4+1][aRow] = a0.y;
            As[nb][aK4+2][aRow] = a0.z; As[nb][aK4+3][aRow] = a0.w;
            As[nb][aK4+0][aRow+64] = a1.x; As[nb][aK4+1][aRow+64] = a1.y;
            As[nb][aK4+2][aRow+64] = a1.z; As[nb][aK4+3][aRow+64] = a1.w;
            if (TB) {
                Bs[nb][aK4+0][aRow] = b0.x; Bs[nb][aK4+1][aRow] = b0.y;
                Bs[nb][aK4+2][aRow] = b0.z; Bs[nb][aK4+3][aRow] = b0.w;
                Bs[nb][aK4+0][aRow+64] = b1.x; Bs[nb][aK4+1][aRow+64] = b1.y;
                Bs[nb][aK4+2][aRow+64] = b1.z; Bs[nb][aK4+3][aRow+64] = b1.w;
            } else {
                *(float4*)&Bs[nb][bK    ][bN4] = b0;
                *(float4*)&Bs[nb][bK + 8][bN4] = b1;
            }
            __syncthreads();
            buf = nb;
        }
    }

    // ---- epilogue ----
    float bb[8];
#pragma unroll
    for (int j = 0; j < 8; j++) bb[j] = bias ? bias[n0 + tx * 8 + j] : 0.0f;

#pragma unroll
    for (int i = 0; i < 8; i++) {
        const long long m = m0 + ty * 8 + i;
        float o[8];
#pragma unroll
        for (int j = 0; j < 8; j++) {
            float v = fmaf(acc[i][j], alpha, bb[j]);
            if (GELU) v = 0.5f * v * (1.0f + erff(v * 0.70710678118654752f));
            o[j] = v;
        }
        *(float4*)&C[m * ldc + n0 + tx * 8    ] = *(float4*)&o[0];
        *(float4*)&C[m * ldc + n0 + tx * 8 + 4] = *(float4*)&o[4];
    }
}

// ---------------- effective MLP bias: edge_features == 1/S analytically ----------
__global__ void bm1eff_kernel(const float* __restrict__ Wm1,
                              const float* __restrict__ bm1,
                              float* __restrict__ out)
{
    int e = blockIdx.x * blockDim.x + threadIdx.x;
    if (e < EMB) {
        float s = 0.0f;
#pragma unroll
        for (int h = 0; h < NH; h++) s += Wm1[(long long)e * W1LD + EMB + h];
        out[e] = bm1[e] + s * (1.0f / (float)SEQ);
    }
}

// ---------------- softmax over j per (b,i,h); emit ew_mean, masked, 1/nn ---------
__global__ __launch_bounds__(256)
void softmax_ew_kernel(const float* __restrict__ scores,
                       float* __restrict__ ewm, float* __restrict__ ewk,
                       float* __restrict__ invnn)
{
    extern __shared__ float sm[];            // NH * SEQ floats
    __shared__ float sinv[NH];
    __shared__ int   scnt[NH];

    const int bi = blockIdx.x;
    const int b  = bi / SEQ;
    const int i  = bi % SEQ;
    const int tid = threadIdx.x;

    const float* base0 = scores + ((size_t)(b * NH) * SEQ + (size_t)i) * SEQ;
    const size_t hstride = (size_t)SEQ * SEQ;

    for (int idx = tid; idx < NH * SEQ; idx += 256) {
        int h = idx >> 11;
        int j = idx & (SEQ - 1);
        sm[idx] = base0[(size_t)h * hstride + j];
    }
    __syncthreads();

    const int w = tid >> 5, lane = tid & 31;
    {
        float m = -1e30f;
        for (int j = lane; j < SEQ; j += 32) m = fmaxf(m, sm[w * SEQ + j]);
#pragma unroll
        for (int o = 16; o > 0; o >>= 1) m = fmaxf(m, __shfl_xor_sync(0xffffffffu, m, o));
        float z = 0.0f;
        for (int j = lane; j < SEQ; j += 32) {
            float e = fast_exp(sm[w * SEQ + j] - m);
            sm[w * SEQ + j] = e;
            z += e;
        }
#pragma unroll
        for (int o = 16; o > 0; o >>= 1) z += __shfl_xor_sync(0xffffffffu, z, o);
        if (lane == 0) sinv[w] = 1.0f / z;
    }
    __syncthreads();

    float inv[NH];
#pragma unroll
    for (int h = 0; h < NH; h++) inv[h] = sinv[h] * (1.0f / (float)NH);

    int cnt = 0;
    const size_t obase = (size_t)bi * SEQ;
    for (int j = tid; j < SEQ; j += 256) {
        float ew = 0.0f;
#pragma unroll
        for (int h = 0; h < NH; h++) ew += sm[h * SEQ + j] * inv[h];
        ewm[obase + j] = ew;
        bool adj = ew > 0.1f;
        ewk[obase + j] = adj ? ew : 0.0f;
        cnt += adj ? 1 : 0;
    }
#pragma unroll
    for (int o = 16; o > 0; o >>= 1) cnt += __shfl_xor_sync(0xffffffffu, cnt, o);
    if (lane == 0) scnt[w] = cnt;
    __syncthreads();
    if (tid == 0) {
        int c = 0;
#pragma unroll
        for (int h = 0; h < NH; h++) c += scnt[h];
        float f = (float)c;
        if (f < 1.0f) f = 1.0f;
        invnn[bi] = 1.0f / f;
    }
}

// ---------------- elementwise: pre += accx * invnn + accv ------------------------
__global__ void combine_kernel(float* __restrict__ pre,
                               const float* __restrict__ accx,
                               const float* __restrict__ accv,
                               const float* __restrict__ invnn)
{
    int idx = blockIdx.x * blockDim.x + threadIdx.x;
    if (idx < BS * EMB) {
        int bi = idx >> 9;
        pre[idx] += accx[idx] * invnn[bi] + accv[idx];
    }
}

// ---------------- driver ---------------------------------------------------------
extern "C" void kernel_launch(void* const* d_in, const int* in_sizes, int n_in,
                              void* d_out, int out_size)
{
    const float* x   = (const float*)d_in[0];
    const float* Wq  = (const float*)d_in[1];
    const float* bq  = (const float*)d_in[2];
    const float* Wk  = (const float*)d_in[3];
    const float* bk  = (const float*)d_in[4];
    const float* Wv  = (const float*)d_in[5];
    const float* bv  = (const float*)d_in[6];
    const float* Wm1 = (const float*)d_in[7];
    const float* bm1 = (const float*)d_in[8];
    const float* Wm2 = (const float*)d_in[9];
    const float* bm2 = (const float*)d_in[10];
    const float* Wo  = (const float*)d_in[11];
    const float* bo  = (const float*)d_in[12];
    float* out = (float*)d_out;

    float *q, *k, *v, *scores, *ewm, *ewk, *invnn, *mid, *pre, *accv, *accx, *bm1eff;
    cudaGetSymbolAddress((void**)&q,      g_q);
    cudaGetSymbolAddress((void**)&k,      g_k);
    cudaGetSymbolAddress((void**)&v,      g_v);
    cudaGetSymbolAddress((void**)&scores, g_scores);
    cudaGetSymbolAddress((void**)&ewm,    g_ewm);
    cudaGetSymbolAddress((void**)&ewk,    g_ewk);
    cudaGetSymbolAddress((void**)&invnn,  g_invnn);
    cudaGetSymbolAddress((void**)&mid,    g_mid);
    cudaGetSymbolAddress((void**)&pre,    g_pre);
    cudaGetSymbolAddress((void**)&accv,   g_accv);
    cudaGetSymbolAddress((void**)&accx,   g_accx);
    cudaGetSymbolAddress((void**)&bm1eff, g_bm1eff);

    // effective MLP bias (edge_features == 1/S analytically)
    bm1eff_kernel<<<1, 512>>>(Wm1, bm1, bm1eff);

    // QKV projections: [4096,512] = x @ W^T + b   grid (512/128, 4096/128)
    dim3 gP(EMB / 128, BS / 128, 1);
    sgemm128<true,  false><<<gP, 256>>>(x, Wq, bq, q, EMB, EMB, EMB, EMB, 0, 0, 0, 1.0f);
    sgemm128<true,  false><<<gP, 256>>>(x, Wk, bk, k, EMB, EMB, EMB, EMB, 0, 0, 0, 1.0f);
    sgemm128<true,  false><<<gP, 256>>>(x, Wv, bv, v, EMB, EMB, EMB, EMB, 0, 0, 0, 1.0f);

    // scores[b,h] = scale * q_h @ k_h^T  (z = head; per-batch launch)
    dim3 gS(SEQ / 128, SEQ / 128, NH);
    for (int b = 0; b < BATCH; b++) {
        sgemm128<true, false><<<gS, 256>>>(
            q + (size_t)b * SEQ * EMB, k + (size_t)b * SEQ * EMB, nullptr,
            scores + (size_t)b * NH * SEQ * SEQ,
            HD, EMB, EMB, SEQ,
            64LL, 64LL, (long long)SEQ * SEQ, 0.125f);
    }

    // softmax + mean-over-heads + threshold mask + neighbor counts
    cudaFuncSetAttribute(softmax_ew_kernel,
                         cudaFuncAttributeMaxDynamicSharedMemorySize, NH * SEQ * 4);
    softmax_ew_kernel<<<BS, 256, NH * SEQ * 4>>>(scores, ewm, ewk, invnn);

    // aggregations: accv = ewm @ v ; accx = ewk @ x  (z = batch)
    dim3 gA(EMB / 128, SEQ / 128, BATCH);
    sgemm128<false, false><<<gA, 256>>>(ewm, v, nullptr, accv, SEQ, SEQ, EMB, EMB,
                                        (long long)SEQ * SEQ, (long long)SEQ * EMB, (long long)SEQ * EMB, 1.0f);
    sgemm128<false, false><<<gA, 256>>>(ewk, x, nullptr, accx, SEQ, SEQ, EMB, EMB,
                                        (long long)SEQ * SEQ, (long long)SEQ * EMB, (long long)SEQ * EMB, 1.0f);

    // gated MLP: mid = gelu(x @ Wm1[:, :E]^T + bm1_eff); pre = mid @ Wm2^T + bm2
    sgemm128<true, true ><<<gP, 256>>>(x,   Wm1, bm1eff, mid, EMB, EMB, W1LD, EMB, 0, 0, 0, 1.0f);
    sgemm128<true, false><<<gP, 256>>>(mid, Wm2, bm2,    pre, EMB, EMB, EMB,  EMB, 0, 0, 0, 1.0f);

    // pre += messages + attended
    combine_kernel<<<(BS * EMB + 255) / 256, 256>>>(pre, accx, accv, invnn);

    // out = pre @ Wo^T + bo
    sgemm128<true, false><<<gP, 256>>>(pre, Wo, bo, out, EMB, EMB, EMB, EMB, 0, 0, 0, 1.0f);
}